// round 6
// baseline (speedup 1.0000x reference)
#include <cuda_runtime.h>
#include <math.h>

#define KHALF 5
#define KW 11
#define MAXB 16
#define MAXT 2048
#define MAXD 512
#define MAXL 160
#define THRESH 0.9f
#define TS 256
#define ROWS_NEED (TS + 2 * KHALF)   // 266
#define ROWS_PAD  288                // 9 passes * 32 rows

typedef unsigned long long u64;

// ---- device scratch ----
__device__ float d_weff[KW * MAXD + 4];     // folded weights; bias at [KW*MAXD]
__device__ float d_apart[MAXB * 8];
__device__ int   d_tfire[MAXB * MAXL];
__device__ int   d_nfinal[MAXB];

__device__ __forceinline__ void ffma2(u64& d, u64 a, u64 b) {
    asm("fma.rn.f32x2 %0, %1, %2, %0;" : "+l"(d) : "l"(a), "l"(b));
}
__device__ __forceinline__ float unpack_sum(u64 v) {
    float x, y;
    asm("mov.b64 {%0,%1}, %2;" : "=f"(x), "=f"(y) : "l"(v));
    return x + y;
}

// ---------------------------------------------------------------------------
// Fused: blocks [0,NW) fold conv*proj weights; blocks [NW,..) zero the output.
__global__ void k_init(const float* __restrict__ cw, const float* __restrict__ cb,
                       const float* __restrict__ pw, const float* __restrict__ pb,
                       int D, int C, int NW, float* out, int n) {
    if ((int)blockIdx.x < NW) {
        int wid  = blockIdx.x * 8 + (threadIdx.x >> 5);
        int lane = threadIdx.x & 31;
        int NE = KW * D;
        if (wid > NE) return;
        float s = 0.f;
        if (wid == NE) {
            for (int c = lane; c < C; c += 32) s += cb[c] * pw[c];
        } else {
            const float* row = cw + (size_t)wid * C;
            for (int c = lane; c < C; c += 32) s += row[c] * pw[c];
        }
#pragma unroll
        for (int o = 16; o > 0; o >>= 1) s += __shfl_xor_sync(0xffffffffu, s, o);
        if (lane == 0) {
            if (wid == NE) d_weff[KW * MAXD] = s + pb[0];
            else           d_weff[wid] = s;
        }
    } else {
        int bm = blockIdx.x - NW;
        int i = bm * blockDim.x + threadIdx.x;
        int stride = (gridDim.x - NW) * blockDim.x;
        int n4 = n >> 2;
        float4 z = make_float4(0.f, 0.f, 0.f, 0.f);
        float4* p4 = (float4*)out;
        for (int j = i; j < n4; j += stride) p4[j] = z;
        for (int j = n4 * 4 + i; j < n; j += stride) out[j] = 0.f;
    }
}

// ---------------------------------------------------------------------------
// Fused conv-dot + band-sum + sigmoid, packed-f32x2 FFMA inner loop.
__global__ void __launch_bounds__(256) k_galpha(const float* __restrict__ e,
                                                float* __restrict__ alpha_out, int T) {
    __shared__ ulonglong2 swz[KW * 128];        // 22.5 KB weights (f32x2 pairs)
    __shared__ float      sg[ROWS_PAD * 12];    // g rows (stride 12)
    __shared__ float      red[256];

    int b  = blockIdx.y;
    int t0 = blockIdx.x * TS;
    int tid = threadIdx.x;
    int wid = tid >> 5, lane = tid & 31;

    {
        const ulonglong2* w2g = (const ulonglong2*)d_weff;
        for (int i = tid; i < KW * 128; i += 256) swz[i] = w2g[i];
    }
    __syncthreads();

    const ulonglong2* e2 = (const ulonglong2*)e;
#pragma unroll 1
    for (int pass = 0; pass < 9; pass++) {
        int rr0 = pass * 32 + wid * 4;
        u64 acc2[KW][4];
#pragma unroll
        for (int k = 0; k < KW; k++)
#pragma unroll
            for (int r = 0; r < 4; r++) acc2[k][r] = 0ULL;

#pragma unroll
        for (int r = 0; r < 4; r++) {
            int rr = rr0 + r;
            int gt = t0 - KHALF + rr;
            if (rr < ROWS_NEED && gt >= 0 && gt < T) {
                size_t base = ((size_t)b * T + gt) * 128;
                ulonglong2 ev[4];
#pragma unroll
                for (int jj = 0; jj < 4; jj++) ev[jj] = e2[base + jj * 32 + lane];
#pragma unroll
                for (int k = 0; k < KW; k++) {
#pragma unroll
                    for (int jj = 0; jj < 4; jj++) {
                        ulonglong2 w2 = swz[k * 128 + jj * 32 + lane];
                        ffma2(acc2[k][r], ev[jj].x, w2.x);
                        ffma2(acc2[k][r], ev[jj].y, w2.y);
                    }
                }
            }
        }
        float accf[KW][4];
#pragma unroll
        for (int k = 0; k < KW; k++)
#pragma unroll
            for (int r = 0; r < 4; r++) {
                float v = unpack_sum(acc2[k][r]);
#pragma unroll
                for (int o = 16; o > 0; o >>= 1) v += __shfl_xor_sync(0xffffffffu, v, o);
                accf[k][r] = v;
            }
        if (lane == 0) {
#pragma unroll
            for (int r = 0; r < 4; r++) {
                float4* g4 = (float4*)(sg + (size_t)(rr0 + r) * 12);
                g4[0] = make_float4(accf[0][r], accf[1][r], accf[2][r],  accf[3][r]);
                g4[1] = make_float4(accf[4][r], accf[5][r], accf[6][r],  accf[7][r]);
                g4[2] = make_float4(accf[8][r], accf[9][r], accf[10][r], 0.f);
            }
        }
    }
    __syncthreads();

    float x = d_weff[KW * MAXD];
#pragma unroll
    for (int k = 0; k < KW; k++) x += sg[(tid + k) * 12 + k];
    float a = 1.0f / (1.0f + expf(-x));
    alpha_out[(size_t)b * T + t0 + tid] = a;

    red[tid] = a;
    __syncthreads();
    for (int s = 128; s > 0; s >>= 1) {
        if (tid < s) red[tid] += red[tid + s];
        __syncthreads();
    }
    if (tid == 0) d_apart[b * 8 + blockIdx.x] = red[0];
}

// ---------------------------------------------------------------------------
// Integrate-and-fire: speculative-FADD serial trace (bit-identical to the
// plain sequential loop), then parallel reconstruction via ballot + popcount.
__global__ void k_scan(const float* __restrict__ alpha_out, float* __restrict__ aws,
                       const int* __restrict__ elens, const int* __restrict__ ylens,
                       int T, int Lp1, int nch) {
    __shared__ float sa[MAXT + 16];
    __shared__ float ss[MAXT + 16];
    __shared__ unsigned sword[MAXT / 32];
    __shared__ int scnt[MAXT / 32];
    __shared__ float s_sum;

    int b = blockIdx.x;
    int tid = threadIdx.x;
    int el = elens[b], yl = ylens[b];

    if (tid == 0) {
        float sum = 0.f;
        for (int c = 0; c < nch; c++) sum += d_apart[b * 8 + c];
        s_sum = sum;
    }
    __syncthreads();
    float sum = s_sum;
    float yf = (float)yl;
    for (int t = tid; t < T; t += 256)
        sa[t] = (alpha_out[(size_t)b * T + t] / sum) * yf;
    for (int t = T + tid; t < T + 16; t += 256) sa[t] = 0.f;
    __syncthreads();

    if (tid == 0) {
        float acc = 0.f;
        int t = 0;
        while (t < el) {
            float s0  = acc + sa[t + 0];
            float s1  = s0  + sa[t + 1];
            float s2  = s1  + sa[t + 2];
            float s3  = s2  + sa[t + 3];
            float s4  = s3  + sa[t + 4];
            float s5  = s4  + sa[t + 5];
            float s6  = s5  + sa[t + 6];
            float s7  = s6  + sa[t + 7];
            float s8  = s7  + sa[t + 8];
            float s9  = s8  + sa[t + 9];
            float s10 = s9  + sa[t + 10];
            float s11 = s10 + sa[t + 11];
            float s12 = s11 + sa[t + 12];
            float s13 = s12 + sa[t + 13];
            float s14 = s13 + sa[t + 14];
            float s15 = s14 + sa[t + 15];
            ss[t + 0]  = s0;  ss[t + 1]  = s1;  ss[t + 2]  = s2;  ss[t + 3]  = s3;
            ss[t + 4]  = s4;  ss[t + 5]  = s5;  ss[t + 6]  = s6;  ss[t + 7]  = s7;
            ss[t + 8]  = s8;  ss[t + 9]  = s9;  ss[t + 10] = s10; ss[t + 11] = s11;
            ss[t + 12] = s12; ss[t + 13] = s13; ss[t + 14] = s14; ss[t + 15] = s15;
            unsigned m = 0;
            m |= (s0  >= THRESH) ? 1u     : 0u;
            m |= (s1  >= THRESH) ? 2u     : 0u;
            m |= (s2  >= THRESH) ? 4u     : 0u;
            m |= (s3  >= THRESH) ? 8u     : 0u;
            m |= (s4  >= THRESH) ? 16u    : 0u;
            m |= (s5  >= THRESH) ? 32u    : 0u;
            m |= (s6  >= THRESH) ? 64u    : 0u;
            m |= (s7  >= THRESH) ? 128u   : 0u;
            m |= (s8  >= THRESH) ? 256u   : 0u;
            m |= (s9  >= THRESH) ? 512u   : 0u;
            m |= (s10 >= THRESH) ? 1024u  : 0u;
            m |= (s11 >= THRESH) ? 2048u  : 0u;
            m |= (s12 >= THRESH) ? 4096u  : 0u;
            m |= (s13 >= THRESH) ? 8192u  : 0u;
            m |= (s14 >= THRESH) ? 16384u : 0u;
            m |= (s15 >= THRESH) ? 32768u : 0u;
            if (m == 0) {
                acc = s15;
                t += 16;
            } else {
                int j = __ffs(m) - 1;
                acc = ss[t + j] + (sa[t + j] - 1.0f);
                t += j + 1;
            }
        }
    }
    __syncthreads();

    for (int t = tid; t < T; t += 256) {
        bool cand = (t < el) && (ss[t] >= THRESH);
        unsigned bal = __ballot_sync(0xffffffffu, cand);
        if ((t & 31) == 0) { sword[t >> 5] = bal; scnt[t >> 5] = __popc(bal); }
    }
    __syncthreads();
    if (tid == 0) {
        int run = 0, nw = T >> 5;
        for (int w = 0; w < nw; w++) { int c = scnt[w]; scnt[w] = run; run += c; }
        d_nfinal[b] = run < yl ? run : yl;
    }
    __syncthreads();
    float* awb = aws + (size_t)b * Lp1 * T;
    for (int t = tid; t < T; t += 256) {
        if (t >= el) continue;
        float s = ss[t];
        float a = sa[t];
        unsigned w = sword[t >> 5];
        int rank = scnt[t >> 5] + __popc(w & ((1u << (t & 31)) - 1u));
        if (rank >= yl) continue;
        bool fire = (s >= THRESH);
        float wold = fire ? (1.0f - s) : a;
        awb[(size_t)rank * T + t] = wold;
        if (fire) {
            awb[(size_t)(rank + 1) * T + t] = s + (a - 1.0f);
            d_tfire[b * MAXL + rank] = t;
        }
    }
}

// ---------------------------------------------------------------------------
// fired[b,l,:] = sum_{t in segment} aws[b,l,t] * eouts[b,t,:]
// Manual unroll-8: batch 8 weight loads + 8 float4 loads per step -> MLP ~16.
__global__ void __launch_bounds__(128) k_fired(const float* __restrict__ e,
                                               const float* __restrict__ aws,
                                               float* __restrict__ fired,
                                               int T, int D, int L) {
    int b = blockIdx.y, l = blockIdx.x;
    if (l >= d_nfinal[b]) return;
    int tlo = (l == 0) ? 0 : d_tfire[b * MAXL + l - 1];
    int thi = d_tfire[b * MAXL + l];
    const float* awr = aws + ((size_t)b * (L + 1) + l) * T;
    const float4* eb = (const float4*)(e + (size_t)b * T * D) + threadIdx.x;
    int D4 = D >> 2;

    float4 acc0 = make_float4(0.f, 0.f, 0.f, 0.f);
    float4 acc1 = make_float4(0.f, 0.f, 0.f, 0.f);

    int t = tlo;
    for (; t + 8 <= thi + 1; t += 8) {
        float w0 = awr[t + 0], w1 = awr[t + 1], w2 = awr[t + 2], w3 = awr[t + 3];
        float w4 = awr[t + 4], w5 = awr[t + 5], w6 = awr[t + 6], w7 = awr[t + 7];
        float4 e0 = eb[(size_t)(t + 0) * D4];
        float4 e1 = eb[(size_t)(t + 1) * D4];
        float4 e2 = eb[(size_t)(t + 2) * D4];
        float4 e3 = eb[(size_t)(t + 3) * D4];
        float4 e4 = eb[(size_t)(t + 4) * D4];
        float4 e5 = eb[(size_t)(t + 5) * D4];
        float4 e6 = eb[(size_t)(t + 6) * D4];
        float4 e7 = eb[(size_t)(t + 7) * D4];
        acc0.x += w0 * e0.x; acc0.y += w0 * e0.y; acc0.z += w0 * e0.z; acc0.w += w0 * e0.w;
        acc1.x += w1 * e1.x; acc1.y += w1 * e1.y; acc1.z += w1 * e1.z; acc1.w += w1 * e1.w;
        acc0.x += w2 * e2.x; acc0.y += w2 * e2.y; acc0.z += w2 * e2.z; acc0.w += w2 * e2.w;
        acc1.x += w3 * e3.x; acc1.y += w3 * e3.y; acc1.z += w3 * e3.z; acc1.w += w3 * e3.w;
        acc0.x += w4 * e4.x; acc0.y += w4 * e4.y; acc0.z += w4 * e4.z; acc0.w += w4 * e4.w;
        acc1.x += w5 * e5.x; acc1.y += w5 * e5.y; acc1.z += w5 * e5.z; acc1.w += w5 * e5.w;
        acc0.x += w6 * e6.x; acc0.y += w6 * e6.y; acc0.z += w6 * e6.z; acc0.w += w6 * e6.w;
        acc1.x += w7 * e7.x; acc1.y += w7 * e7.y; acc1.z += w7 * e7.z; acc1.w += w7 * e7.w;
    }
    for (; t <= thi; t++) {
        float w = awr[t];
        float4 ev = eb[(size_t)t * D4];
        acc0.x += w * ev.x; acc0.y += w * ev.y;
        acc0.z += w * ev.z; acc0.w += w * ev.w;
    }
    acc0.x += acc1.x; acc0.y += acc1.y; acc0.z += acc1.z; acc0.w += acc1.w;
    ((float4*)(fired + ((size_t)b * L + l) * D))[threadIdx.x] = acc0;
}

// ---------------------------------------------------------------------------
extern "C" void kernel_launch(void* const* d_in, const int* in_sizes, int n_in,
                              void* d_out, int out_size) {
    const float* eouts  = (const float*)d_in[0];
    const float* conv_w = (const float*)d_in[1];
    const float* conv_b = (const float*)d_in[2];
    const float* proj_w = (const float*)d_in[3];
    const float* proj_b = (const float*)d_in[4];
    const int*   elens  = (const int*)d_in[5];
    const int*   ylens  = (const int*)d_in[6];

    int B = in_sizes[5];
    int C = in_sizes[2];
    int D = in_sizes[1] / (KW * C);
    int T = in_sizes[0] / (B * D);
    int L = (out_size - 2 * B * T) / (B * (D + T));

    float* fired   = (float*)d_out;
    float* alpha_o = fired + (size_t)B * L * D;
    float* aws     = alpha_o + (size_t)B * T;

    int NW = (KW * D + 1 + 7) / 8;

    k_init<<<NW + 512, 256>>>(conv_w, conv_b, proj_w, proj_b, D, C, NW,
                              (float*)d_out, out_size);
    k_galpha<<<dim3(T / TS, B), 256>>>(eouts, alpha_o, T);
    k_scan<<<B, 256>>>(alpha_o, aws, elens, ylens, T, L + 1, T / TS);
    k_fired<<<dim3(L, B), 128>>>(eouts, aws, fired, T, D, L);
}

// round 11
// speedup vs baseline: 1.0862x; 1.0862x over previous
#include <cuda_runtime.h>
#include <math.h>

#define KHALF 5
#define KW 11
#define MAXB 16
#define MAXT 2048
#define MAXD 512
#define MAXL 160
#define THRESH 0.9f
#define TS 256
#define ROWS_NEED (TS + 2 * KHALF)   // 266
#define ROWS_PAD  288                // 9 passes * 32 rows

// ---- device scratch ----
__device__ float d_weff[KW * MAXD + 4];     // folded weights; bias at [KW*MAXD]
__device__ float d_apart[MAXB * 8];
__device__ int   d_tfire[MAXB * MAXL];
__device__ int   d_nfinal[MAXB];

// ---------------------------------------------------------------------------
// Fused: blocks [0,NW) fold conv*proj weights; blocks [NW,..) zero the output.
__global__ void k_init(const float* __restrict__ cw, const float* __restrict__ cb,
                       const float* __restrict__ pw, const float* __restrict__ pb,
                       int D, int C, int NW, float* out, int n) {
    if ((int)blockIdx.x < NW) {
        int wid  = blockIdx.x * 8 + (threadIdx.x >> 5);
        int lane = threadIdx.x & 31;
        int NE = KW * D;
        if (wid > NE) return;
        float s = 0.f;
        if (wid == NE) {
            for (int c = lane; c < C; c += 32) s += cb[c] * pw[c];
        } else {
            const float* row = cw + (size_t)wid * C;
            for (int c = lane; c < C; c += 32) s += row[c] * pw[c];
        }
#pragma unroll
        for (int o = 16; o > 0; o >>= 1) s += __shfl_xor_sync(0xffffffffu, s, o);
        if (lane == 0) {
            if (wid == NE) d_weff[KW * MAXD] = s + pb[0];
            else           d_weff[wid] = s;
        }
    } else {
        int bm = blockIdx.x - NW;
        int i = bm * blockDim.x + threadIdx.x;
        int stride = (gridDim.x - NW) * blockDim.x;
        int n4 = n >> 2;
        float4 z = make_float4(0.f, 0.f, 0.f, 0.f);
        float4* p4 = (float4*)out;
        for (int j = i; j < n4; j += stride) p4[j] = z;
        for (int j = n4 * 4 + i; j < n; j += stride) out[j] = 0.f;
    }
}

// ---------------------------------------------------------------------------
// Fused conv-dot + band-sum + sigmoid (scalar float4 inner loop).
__global__ void __launch_bounds__(256) k_galpha(const float* __restrict__ e,
                                                float* __restrict__ alpha_out, int T) {
    __shared__ float4 swz[KW * 128];            // 22.5 KB weights
    __shared__ float  sg[ROWS_PAD * 12];        // g rows (stride 12)
    __shared__ float  red[256];

    int b  = blockIdx.y;
    int t0 = blockIdx.x * TS;
    int tid = threadIdx.x;
    int wid = tid >> 5, lane = tid & 31;

    {
        const float4* w4g = (const float4*)d_weff;
        for (int i = tid; i < KW * 128; i += 256) swz[i] = w4g[i];
    }
    __syncthreads();

    const float4* e4 = (const float4*)e;
#pragma unroll 1
    for (int pass = 0; pass < 9; pass++) {
        int rr0 = pass * 32 + wid * 4;
        float acc[KW][4];
#pragma unroll
        for (int k = 0; k < KW; k++)
#pragma unroll
            for (int r = 0; r < 4; r++) acc[k][r] = 0.f;

#pragma unroll
        for (int r = 0; r < 4; r++) {
            int rr = rr0 + r;
            int gt = t0 - KHALF + rr;
            if (rr < ROWS_NEED && gt >= 0 && gt < T) {
                size_t base = ((size_t)b * T + gt) * 128;
                float4 ev[4];
#pragma unroll
                for (int jj = 0; jj < 4; jj++) ev[jj] = e4[base + jj * 32 + lane];
#pragma unroll
                for (int k = 0; k < KW; k++) {
#pragma unroll
                    for (int jj = 0; jj < 4; jj++) {
                        float4 w4 = swz[k * 128 + jj * 32 + lane];
                        acc[k][r] += ev[jj].x * w4.x;
                        acc[k][r] += ev[jj].y * w4.y;
                        acc[k][r] += ev[jj].z * w4.z;
                        acc[k][r] += ev[jj].w * w4.w;
                    }
                }
            }
        }
#pragma unroll
        for (int k = 0; k < KW; k++)
#pragma unroll
            for (int r = 0; r < 4; r++) {
                float v = acc[k][r];
#pragma unroll
                for (int o = 16; o > 0; o >>= 1) v += __shfl_xor_sync(0xffffffffu, v, o);
                acc[k][r] = v;
            }
        if (lane == 0) {
#pragma unroll
            for (int r = 0; r < 4; r++) {
                float4* g4 = (float4*)(sg + (size_t)(rr0 + r) * 12);
                g4[0] = make_float4(acc[0][r], acc[1][r], acc[2][r],  acc[3][r]);
                g4[1] = make_float4(acc[4][r], acc[5][r], acc[6][r],  acc[7][r]);
                g4[2] = make_float4(acc[8][r], acc[9][r], acc[10][r], 0.f);
            }
        }
    }
    __syncthreads();

    float x = d_weff[KW * MAXD];
#pragma unroll
    for (int k = 0; k < KW; k++) x += sg[(tid + k) * 12 + k];
    float a = 1.0f / (1.0f + expf(-x));
    alpha_out[(size_t)b * T + t0 + tid] = a;

    red[tid] = a;
    __syncthreads();
    for (int s = 128; s > 0; s >>= 1) {
        if (tid < s) red[tid] += red[tid + s];
        __syncthreads();
    }
    if (tid == 0) d_apart[b * 8 + blockIdx.x] = red[0];
}

// ---------------------------------------------------------------------------
// Integrate-and-fire: speculative-FADD serial trace (bit-identical to the
// plain sequential loop), then parallel reconstruction via ballot + popcount.
__global__ void k_scan(const float* __restrict__ alpha_out, float* __restrict__ aws,
                       const int* __restrict__ elens, const int* __restrict__ ylens,
                       int T, int Lp1, int nch) {
    __shared__ float sa[MAXT + 16];
    __shared__ float ss[MAXT + 16];
    __shared__ unsigned sword[MAXT / 32];
    __shared__ int scnt[MAXT / 32];
    __shared__ float s_sum;

    int b = blockIdx.x;
    int tid = threadIdx.x;
    int el = elens[b], yl = ylens[b];

    if (tid == 0) {
        float sum = 0.f;
        for (int c = 0; c < nch; c++) sum += d_apart[b * 8 + c];
        s_sum = sum;
    }
    __syncthreads();
    float sum = s_sum;
    float yf = (float)yl;
    for (int t = tid; t < T; t += 256)
        sa[t] = (alpha_out[(size_t)b * T + t] / sum) * yf;
    for (int t = T + tid; t < T + 16; t += 256) sa[t] = 0.f;
    __syncthreads();

    if (tid == 0) {
        float acc = 0.f;
        int t = 0;
        while (t < el) {
            float s0  = acc + sa[t + 0];
            float s1  = s0  + sa[t + 1];
            float s2  = s1  + sa[t + 2];
            float s3  = s2  + sa[t + 3];
            float s4  = s3  + sa[t + 4];
            float s5  = s4  + sa[t + 5];
            float s6  = s5  + sa[t + 6];
            float s7  = s6  + sa[t + 7];
            float s8  = s7  + sa[t + 8];
            float s9  = s8  + sa[t + 9];
            float s10 = s9  + sa[t + 10];
            float s11 = s10 + sa[t + 11];
            float s12 = s11 + sa[t + 12];
            float s13 = s12 + sa[t + 13];
            float s14 = s13 + sa[t + 14];
            float s15 = s14 + sa[t + 15];
            ss[t + 0]  = s0;  ss[t + 1]  = s1;  ss[t + 2]  = s2;  ss[t + 3]  = s3;
            ss[t + 4]  = s4;  ss[t + 5]  = s5;  ss[t + 6]  = s6;  ss[t + 7]  = s7;
            ss[t + 8]  = s8;  ss[t + 9]  = s9;  ss[t + 10] = s10; ss[t + 11] = s11;
            ss[t + 12] = s12; ss[t + 13] = s13; ss[t + 14] = s14; ss[t + 15] = s15;
            unsigned m = 0;
            m |= (s0  >= THRESH) ? 1u     : 0u;
            m |= (s1  >= THRESH) ? 2u     : 0u;
            m |= (s2  >= THRESH) ? 4u     : 0u;
            m |= (s3  >= THRESH) ? 8u     : 0u;
            m |= (s4  >= THRESH) ? 16u    : 0u;
            m |= (s5  >= THRESH) ? 32u    : 0u;
            m |= (s6  >= THRESH) ? 64u    : 0u;
            m |= (s7  >= THRESH) ? 128u   : 0u;
            m |= (s8  >= THRESH) ? 256u   : 0u;
            m |= (s9  >= THRESH) ? 512u   : 0u;
            m |= (s10 >= THRESH) ? 1024u  : 0u;
            m |= (s11 >= THRESH) ? 2048u  : 0u;
            m |= (s12 >= THRESH) ? 4096u  : 0u;
            m |= (s13 >= THRESH) ? 8192u  : 0u;
            m |= (s14 >= THRESH) ? 16384u : 0u;
            m |= (s15 >= THRESH) ? 32768u : 0u;
            if (m == 0) {
                acc = s15;
                t += 16;
            } else {
                int j = __ffs(m) - 1;
                acc = ss[t + j] + (sa[t + j] - 1.0f);
                t += j + 1;
            }
        }
    }
    __syncthreads();

    for (int t = tid; t < T; t += 256) {
        bool cand = (t < el) && (ss[t] >= THRESH);
        unsigned bal = __ballot_sync(0xffffffffu, cand);
        if ((t & 31) == 0) { sword[t >> 5] = bal; scnt[t >> 5] = __popc(bal); }
    }
    __syncthreads();
    if (tid == 0) {
        int run = 0, nw = T >> 5;
        for (int w = 0; w < nw; w++) { int c = scnt[w]; scnt[w] = run; run += c; }
        d_nfinal[b] = run < yl ? run : yl;
    }
    __syncthreads();
    float* awb = aws + (size_t)b * Lp1 * T;
    for (int t = tid; t < T; t += 256) {
        if (t >= el) continue;
        float s = ss[t];
        float a = sa[t];
        unsigned w = sword[t >> 5];
        int rank = scnt[t >> 5] + __popc(w & ((1u << (t & 31)) - 1u));
        if (rank >= yl) continue;
        bool fire = (s >= THRESH);
        float wold = fire ? (1.0f - s) : a;
        awb[(size_t)rank * T + t] = wold;
        if (fire) {
            awb[(size_t)(rank + 1) * T + t] = s + (a - 1.0f);
            d_tfire[b * MAXL + rank] = t;
        }
    }
}

// ---------------------------------------------------------------------------
// fired[b,l,:] = sum_{t in segment} aws[b,l,t] * eouts[b,t,:]
// 512 threads = 4 t-interleaved groups x 128 col-threads. Long segments'
// critical path is split 4x; fixed-order smem reduction keeps determinism.
__global__ void __launch_bounds__(512) k_fired(const float* __restrict__ e,
                                               const float* __restrict__ aws,
                                               float* __restrict__ fired,
                                               int T, int D, int L) {
    __shared__ float4 part[3][128];
    int b = blockIdx.y, l = blockIdx.x;
    if (l >= d_nfinal[b]) return;
    int tlo = (l == 0) ? 0 : d_tfire[b * MAXL + l - 1];
    int thi = d_tfire[b * MAXL + l];
    int g = threadIdx.x >> 7;          // 0..3
    int c = threadIdx.x & 127;         // float4 column
    int D4 = D >> 2;
    const float* awr = aws + ((size_t)b * (L + 1) + l) * T;
    const float4* eb = (const float4*)(e + (size_t)b * T * D) + c;

    float4 a0 = make_float4(0.f, 0.f, 0.f, 0.f);
    float4 a1 = make_float4(0.f, 0.f, 0.f, 0.f);

    int t = tlo + g;
    for (; t + 4 <= thi; t += 8) {
        float w0 = awr[t];
        float w1 = awr[t + 4];
        float4 e0 = eb[(size_t)t * D4];
        float4 e1 = eb[(size_t)(t + 4) * D4];
        a0.x += w0 * e0.x; a0.y += w0 * e0.y; a0.z += w0 * e0.z; a0.w += w0 * e0.w;
        a1.x += w1 * e1.x; a1.y += w1 * e1.y; a1.z += w1 * e1.z; a1.w += w1 * e1.w;
    }
    for (; t <= thi; t += 4) {
        float w0 = awr[t];
        float4 e0 = eb[(size_t)t * D4];
        a0.x += w0 * e0.x; a0.y += w0 * e0.y; a0.z += w0 * e0.z; a0.w += w0 * e0.w;
    }
    a0.x += a1.x; a0.y += a1.y; a0.z += a1.z; a0.w += a1.w;

    if (g) part[g - 1][c] = a0;
    __syncthreads();
    if (g == 0) {
        float4 p0 = part[0][c], p1 = part[1][c], p2 = part[2][c];
        a0.x += p0.x; a0.y += p0.y; a0.z += p0.z; a0.w += p0.w;
        a0.x += p1.x; a0.y += p1.y; a0.z += p1.z; a0.w += p1.w;
        a0.x += p2.x; a0.y += p2.y; a0.z += p2.z; a0.w += p2.w;
        ((float4*)(fired + ((size_t)b * L + l) * D))[c] = a0;
    }
}

// ---------------------------------------------------------------------------
extern "C" void kernel_launch(void* const* d_in, const int* in_sizes, int n_in,
                              void* d_out, int out_size) {
    const float* eouts  = (const float*)d_in[0];
    const float* conv_w = (const float*)d_in[1];
    const float* conv_b = (const float*)d_in[2];
    const float* proj_w = (const float*)d_in[3];
    const float* proj_b = (const float*)d_in[4];
    const int*   elens  = (const int*)d_in[5];
    const int*   ylens  = (const int*)d_in[6];

    int B = in_sizes[5];
    int C = in_sizes[2];
    int D = in_sizes[1] / (KW * C);
    int T = in_sizes[0] / (B * D);
    int L = (out_size - 2 * B * T) / (B * (D + T));

    float* fired   = (float*)d_out;
    float* alpha_o = fired + (size_t)B * L * D;
    float* aws     = alpha_o + (size_t)B * T;

    int NW = (KW * D + 1 + 7) / 8;

    k_init<<<NW + 512, 256>>>(conv_w, conv_b, proj_w, proj_b, D, C, NW,
                              (float*)d_out, out_size);
    k_galpha<<<dim3(T / TS, B), 256>>>(eouts, alpha_o, T);
    k_scan<<<B, 256>>>(alpha_o, aws, elens, ylens, T, L + 1, T / TS);
    k_fired<<<dim3(L, B), 512>>>(eouts, aws, fired, T, D, L);
}

// round 12
// speedup vs baseline: 1.2634x; 1.1631x over previous
#include <cuda_runtime.h>
#include <math.h>

#define KHALF 5
#define KW 11
#define MAXB 16
#define MAXT 2048
#define MAXD 512
#define MAXL 160
#define THRESH 0.9f
#define TS 128
#define ROWS_NEED (TS + 2 * KHALF)   // 138
#define NPASS 9                      // 9 * 16 rows = 144 >= 138

typedef unsigned long long u64;

// ---- device scratch ----
__device__ float d_weff[KW * MAXD + 4];     // folded weights; bias at [KW*MAXD]
__device__ float d_apart[MAXB * 16];
__device__ int   d_tfire[MAXB * MAXL];
__device__ int   d_nfinal[MAXB];

__device__ __forceinline__ void ffma2(u64& d, u64 a, u64 b) {
    asm("fma.rn.f32x2 %0, %1, %2, %0;" : "+l"(d) : "l"(a), "l"(b));
}
__device__ __forceinline__ float unpack_sum(u64 v) {
    float x, y;
    asm("mov.b64 {%0,%1}, %2;" : "=f"(x), "=f"(y) : "l"(v));
    return x + y;
}

// ---------------------------------------------------------------------------
// weff fold only (memset work moved into k_galpha / k_fired).
__global__ void k_init(const float* __restrict__ cw, const float* __restrict__ cb,
                       const float* __restrict__ pw, const float* __restrict__ pb,
                       int D, int C) {
    int wid  = blockIdx.x * 8 + (threadIdx.x >> 5);
    int lane = threadIdx.x & 31;
    int NE = KW * D;
    if (wid > NE) return;
    float s = 0.f;
    if (wid == NE) {
        for (int c = lane; c < C; c += 32) s += cb[c] * pw[c];
    } else {
        const float* row = cw + (size_t)wid * C;
        for (int c = lane; c < C; c += 32) s += row[c] * pw[c];
    }
#pragma unroll
    for (int o = 16; o > 0; o >>= 1) s += __shfl_xor_sync(0xffffffffu, s, o);
    if (lane == 0) {
        if (wid == NE) d_weff[KW * MAXD] = s + pb[0];
        else           d_weff[wid] = s;
    }
}

// ---------------------------------------------------------------------------
// Fused conv-dot + band-sum + sigmoid. Packed f32x2 FFMA, 2 blocks/SM.
// Each block also zeroes a grid-stride slice of the aws output region.
__global__ void __launch_bounds__(256, 2) k_galpha(const float* __restrict__ e,
                                                   float* __restrict__ alpha_out,
                                                   float* __restrict__ zp, int nz,
                                                   int T) {
    __shared__ ulonglong2 swz[KW * 128];     // 22.5 KB weights (4 floats per entry)
    __shared__ float      sg[NPASS * 16 * 24]; // 144 rows * 24 (11k x 2 partials) = 13.5 KB
    __shared__ float      red[128];

    int b  = blockIdx.y;
    int t0 = blockIdx.x * TS;
    int tid = threadIdx.x;
    int wid = tid >> 5, lane = tid & 31;

    // zero a slice of the aws region (overlaps with weight load / compute)
    {
        int blk = blockIdx.y * gridDim.x + blockIdx.x;
        int nz4 = nz >> 2;
        float4 z4 = make_float4(0.f, 0.f, 0.f, 0.f);
        float4* zp4 = (float4*)zp;
        for (int i = blk * 256 + tid; i < nz4; i += 256 * 256) zp4[i] = z4;
        if (blk == 0) for (int i = nz4 * 4 + tid; i < nz; i += 256) zp[i] = 0.f;
    }
    {
        const ulonglong2* w2g = (const ulonglong2*)d_weff;
        for (int i = tid; i < KW * 128; i += 256) swz[i] = w2g[i];
    }
    __syncthreads();

    const ulonglong2* e2 = (const ulonglong2*)e;
    const ulonglong2 zz = make_ulonglong2(0ULL, 0ULL);
#pragma unroll 1
    for (int pass = 0; pass < NPASS; pass++) {
        int rr0 = pass * 16 + wid * 2;
        u64 acc[KW][2];
#pragma unroll
        for (int k = 0; k < KW; k++) { acc[k][0] = 0ULL; acc[k][1] = 0ULL; }

        ulonglong2 ev[2][4];
#pragma unroll
        for (int r = 0; r < 2; r++) {
            int rr = rr0 + r;
            int gt = t0 - KHALF + rr;
            bool ok = (rr < ROWS_NEED) && (gt >= 0) && (gt < T);
            size_t base = ((size_t)b * T + gt) * 128;
#pragma unroll
            for (int jj = 0; jj < 4; jj++)
                ev[r][jj] = ok ? e2[base + jj * 32 + lane] : zz;
        }
#pragma unroll
        for (int k = 0; k < KW; k++) {
#pragma unroll
            for (int jj = 0; jj < 4; jj++) {
                ulonglong2 w2 = swz[k * 128 + jj * 32 + lane];
                ffma2(acc[k][0], ev[0][jj].x, w2.x);
                ffma2(acc[k][0], ev[0][jj].y, w2.y);
                ffma2(acc[k][1], ev[1][jj].x, w2.x);
                ffma2(acc[k][1], ev[1][jj].y, w2.y);
            }
        }
        // reduce 32 lanes -> 2 partials (offsets 16,8,4,2); lanes 0,1 store
#pragma unroll
        for (int k = 0; k < KW; k++) {
#pragma unroll
            for (int r = 0; r < 2; r++) {
                float v = unpack_sum(acc[k][r]);
                v += __shfl_xor_sync(0xffffffffu, v, 16);
                v += __shfl_xor_sync(0xffffffffu, v, 8);
                v += __shfl_xor_sync(0xffffffffu, v, 4);
                v += __shfl_xor_sync(0xffffffffu, v, 2);
                if (lane < 2) sg[(rr0 + r) * 24 + k * 2 + lane] = v;
            }
        }
    }
    __syncthreads();

    // alpha for t = t0 + tid (first 128 threads)
    float a = 0.f;
    if (tid < TS) {
        float x = d_weff[KW * MAXD];
#pragma unroll
        for (int k = 0; k < KW; k++)
            x += sg[(tid + k) * 24 + k * 2] + sg[(tid + k) * 24 + k * 2 + 1];
        a = 1.0f / (1.0f + expf(-x));
        alpha_out[(size_t)b * T + t0 + tid] = a;
        red[tid] = a;
    }
    __syncthreads();
    for (int s = 64; s > 0; s >>= 1) {
        if (tid < s) red[tid] += red[tid + s];
        __syncthreads();
    }
    if (tid == 0) d_apart[b * 16 + blockIdx.x] = red[0];
}

// ---------------------------------------------------------------------------
// Integrate-and-fire: speculative-FADD serial trace (bit-identical to the
// plain sequential loop), then parallel reconstruction via ballot + popcount.
__global__ void k_scan(const float* __restrict__ alpha_out, float* __restrict__ aws,
                       const int* __restrict__ elens, const int* __restrict__ ylens,
                       int T, int Lp1, int nch) {
    __shared__ float sa[MAXT + 16];
    __shared__ float ss[MAXT + 16];
    __shared__ unsigned sword[MAXT / 32];
    __shared__ int scnt[MAXT / 32];
    __shared__ float s_sum;

    int b = blockIdx.x;
    int tid = threadIdx.x;
    int el = elens[b], yl = ylens[b];

    if (tid == 0) {
        float sum = 0.f;
        for (int c = 0; c < nch; c++) sum += d_apart[b * 16 + c];
        s_sum = sum;
    }
    __syncthreads();
    float sum = s_sum;
    float yf = (float)yl;
    for (int t = tid; t < T; t += 256)
        sa[t] = (alpha_out[(size_t)b * T + t] / sum) * yf;
    for (int t = T + tid; t < T + 16; t += 256) sa[t] = 0.f;
    __syncthreads();

    if (tid == 0) {
        float acc = 0.f;
        int t = 0;
        while (t < el) {
            float s0  = acc + sa[t + 0];
            float s1  = s0  + sa[t + 1];
            float s2  = s1  + sa[t + 2];
            float s3  = s2  + sa[t + 3];
            float s4  = s3  + sa[t + 4];
            float s5  = s4  + sa[t + 5];
            float s6  = s5  + sa[t + 6];
            float s7  = s6  + sa[t + 7];
            float s8  = s7  + sa[t + 8];
            float s9  = s8  + sa[t + 9];
            float s10 = s9  + sa[t + 10];
            float s11 = s10 + sa[t + 11];
            float s12 = s11 + sa[t + 12];
            float s13 = s12 + sa[t + 13];
            float s14 = s13 + sa[t + 14];
            float s15 = s14 + sa[t + 15];
            ss[t + 0]  = s0;  ss[t + 1]  = s1;  ss[t + 2]  = s2;  ss[t + 3]  = s3;
            ss[t + 4]  = s4;  ss[t + 5]  = s5;  ss[t + 6]  = s6;  ss[t + 7]  = s7;
            ss[t + 8]  = s8;  ss[t + 9]  = s9;  ss[t + 10] = s10; ss[t + 11] = s11;
            ss[t + 12] = s12; ss[t + 13] = s13; ss[t + 14] = s14; ss[t + 15] = s15;
            unsigned m = 0;
            m |= (s0  >= THRESH) ? 1u     : 0u;
            m |= (s1  >= THRESH) ? 2u     : 0u;
            m |= (s2  >= THRESH) ? 4u     : 0u;
            m |= (s3  >= THRESH) ? 8u     : 0u;
            m |= (s4  >= THRESH) ? 16u    : 0u;
            m |= (s5  >= THRESH) ? 32u    : 0u;
            m |= (s6  >= THRESH) ? 64u    : 0u;
            m |= (s7  >= THRESH) ? 128u   : 0u;
            m |= (s8  >= THRESH) ? 256u   : 0u;
            m |= (s9  >= THRESH) ? 512u   : 0u;
            m |= (s10 >= THRESH) ? 1024u  : 0u;
            m |= (s11 >= THRESH) ? 2048u  : 0u;
            m |= (s12 >= THRESH) ? 4096u  : 0u;
            m |= (s13 >= THRESH) ? 8192u  : 0u;
            m |= (s14 >= THRESH) ? 16384u : 0u;
            m |= (s15 >= THRESH) ? 32768u : 0u;
            if (m == 0) {
                acc = s15;
                t += 16;
            } else {
                int j = __ffs(m) - 1;
                acc = ss[t + j] + (sa[t + j] - 1.0f);
                t += j + 1;
            }
        }
    }
    __syncthreads();

    for (int t = tid; t < T; t += 256) {
        bool cand = (t < el) && (ss[t] >= THRESH);
        unsigned bal = __ballot_sync(0xffffffffu, cand);
        if ((t & 31) == 0) { sword[t >> 5] = bal; scnt[t >> 5] = __popc(bal); }
    }
    __syncthreads();
    if (tid == 0) {
        int run = 0, nw = T >> 5;
        for (int w = 0; w < nw; w++) { int c = scnt[w]; scnt[w] = run; run += c; }
        d_nfinal[b] = run < yl ? run : yl;
    }
    __syncthreads();
    float* awb = aws + (size_t)b * Lp1 * T;
    for (int t = tid; t < T; t += 256) {
        if (t >= el) continue;
        float s = ss[t];
        float a = sa[t];
        unsigned w = sword[t >> 5];
        int rank = scnt[t >> 5] + __popc(w & ((1u << (t & 31)) - 1u));
        if (rank >= yl) continue;
        bool fire = (s >= THRESH);
        float wold = fire ? (1.0f - s) : a;
        awb[(size_t)rank * T + t] = wold;
        if (fire) {
            awb[(size_t)(rank + 1) * T + t] = s + (a - 1.0f);
            d_tfire[b * MAXL + rank] = t;
        }
    }
}

// ---------------------------------------------------------------------------
// fired[b,l,:] = sum_{t in segment} aws[b,l,t] * eouts[b,t,:]
// 1024 threads = 8 t-interleaved groups x 128 col-threads. Unfired slots
// (l >= nfinal) are zero-filled here (no separate memset).
__global__ void __launch_bounds__(1024) k_fired(const float* __restrict__ e,
                                                const float* __restrict__ aws,
                                                float* __restrict__ fired,
                                                int T, int D, int L) {
    __shared__ float4 part[7][128];
    int b = blockIdx.y, l = blockIdx.x;
    int g = threadIdx.x >> 7;          // 0..7
    int c = threadIdx.x & 127;         // float4 column
    float4* outp = (float4*)(fired + ((size_t)b * L + l) * D);

    if (l >= d_nfinal[b]) {
        if (threadIdx.x < 128) outp[c] = make_float4(0.f, 0.f, 0.f, 0.f);
        return;
    }
    int tlo = (l == 0) ? 0 : d_tfire[b * MAXL + l - 1];
    int thi = d_tfire[b * MAXL + l];
    int D4 = D >> 2;
    const float* awr = aws + ((size_t)b * (L + 1) + l) * T;
    const float4* eb = (const float4*)(e + (size_t)b * T * D) + c;

    float4 a0 = make_float4(0.f, 0.f, 0.f, 0.f);
    float4 a1 = make_float4(0.f, 0.f, 0.f, 0.f);

    int t = tlo + g;
    for (; t + 8 <= thi; t += 16) {
        float w0 = awr[t];
        float w1 = awr[t + 8];
        float4 e0 = eb[(size_t)t * D4];
        float4 e1 = eb[(size_t)(t + 8) * D4];
        a0.x += w0 * e0.x; a0.y += w0 * e0.y; a0.z += w0 * e0.z; a0.w += w0 * e0.w;
        a1.x += w1 * e1.x; a1.y += w1 * e1.y; a1.z += w1 * e1.z; a1.w += w1 * e1.w;
    }
    for (; t <= thi; t += 8) {
        float w0 = awr[t];
        float4 e0 = eb[(size_t)t * D4];
        a0.x += w0 * e0.x; a0.y += w0 * e0.y; a0.z += w0 * e0.z; a0.w += w0 * e0.w;
    }
    a0.x += a1.x; a0.y += a1.y; a0.z += a1.z; a0.w += a1.w;

    if (g) part[g - 1][c] = a0;
    __syncthreads();
    if (g == 0) {
#pragma unroll
        for (int p = 0; p < 7; p++) {
            float4 pp = part[p][c];
            a0.x += pp.x; a0.y += pp.y; a0.z += pp.z; a0.w += pp.w;
        }
        outp[c] = a0;
    }
}

// ---------------------------------------------------------------------------
extern "C" void kernel_launch(void* const* d_in, const int* in_sizes, int n_in,
                              void* d_out, int out_size) {
    const float* eouts  = (const float*)d_in[0];
    const float* conv_w = (const float*)d_in[1];
    const float* conv_b = (const float*)d_in[2];
    const float* proj_w = (const float*)d_in[3];
    const float* proj_b = (const float*)d_in[4];
    const int*   elens  = (const int*)d_in[5];
    const int*   ylens  = (const int*)d_in[6];

    int B = in_sizes[5];
    int C = in_sizes[2];
    int D = in_sizes[1] / (KW * C);
    int T = in_sizes[0] / (B * D);
    int L = (out_size - 2 * B * T) / (B * (D + T));

    float* fired   = (float*)d_out;
    float* alpha_o = fired + (size_t)B * L * D;
    float* aws     = alpha_o + (size_t)B * T;
    int    nzero   = out_size - B * L * D - B * T;   // aws region (+tail)

    int NW = (KW * D + 1 + 7) / 8;

    k_init<<<NW, 256>>>(conv_w, conv_b, proj_w, proj_b, D, C);
    k_galpha<<<dim3(T / TS, B), 256>>>(eouts, alpha_o, aws, nzero, T);
    k_scan<<<B, 256>>>(alpha_o, aws, elens, ylens, T, L + 1, T / TS);
    k_fired<<<dim3(L, B), 1024>>>(eouts, aws, fired, T, D, L);
}